// round 8
// baseline (speedup 1.0000x reference)
#include <cuda_runtime.h>

// v: [8][1024][8][64] f32, w: [1][8][63] f32, out: [8][1024][8][64] f32
// out[n,j,h,d] = A[n,h,a,d] + B[n,h,b,d],  j = a*32+b
//   A = bias @ R,  B = bias @ C
//   R[c,d] = sum_e v[n, c*32+e, h, d],  C[e,d] = sum_c v[n, c*32+e, h, d]
//   bias[h,j,k] = w[h, (32 - k + j) mod 63]
//
// Single kernel, grid=128 (n,h,d-half), 512 threads, 1 block/SM.
// v-slice (128KB) staged to smem ONCE via cp.async; R/C sums + matvec from
// smem; out written with streaming stores.

#define SV_BYTES   131072                       // 1024 rows x 32 floats
#define SMEM_BYTES (SV_BYTES + 8192 + 8192 + 4096 + 4096 + 4224)

__device__ __forceinline__ void cp_async16(void* smem_dst, const void* gmem_src) {
    unsigned s = (unsigned)__cvta_generic_to_shared(smem_dst);
    asm volatile("cp.async.cg.shared.global [%0], [%1], 16;\n" :: "r"(s), "l"(gmem_src));
}

__global__ __launch_bounds__(512, 1)
void fused_kernel(const float4* __restrict__ v4,
                  const float*  __restrict__ w,
                  float4* __restrict__ out4) {
    int blk = blockIdx.x;          // 0..127
    int q = blk & 1;               // d-half: float4 cols [q*8, q*8+8)
    int h = (blk >> 1) & 7;
    int n = blk >> 4;              // 0..7
    int tid = threadIdx.x;

    extern __shared__ char smem[];
    float4* sv  = (float4*)smem;                      // [1024][8] float4
    float4* sRp = (float4*)(smem + SV_BYTES);         // [2][32][8]
    float4* sCp = sRp + 512;                          // [2][32][8]
    float4* sA  = sCp + 512;                          // [32][8]
    float4* sB  = sA + 256;                           // [32][8]
    float*  sb  = (float*)(sB + 256);                 // [32][33]

    const float4* base = v4 + ((size_t)n * 1024) * 128 + h * 16 + q * 8;

    // ---- Stage v slice: 1024 rows x 128B, one 16B cp.async per (row,col) ----
    {
        int rg  = tid >> 3;          // 0..63
        int col = tid & 7;           // 0..7
        #pragma unroll
        for (int i = 0; i < 16; ++i) {
            int row = i * 64 + rg;
            cp_async16(&sv[row * 8 + col], base + (size_t)row * 128 + col);
        }
        asm volatile("cp.async.commit_group;\n" ::: "memory");
    }

    // ---- bias tile (overlaps with async staging) ----
    #pragma unroll
    for (int idx = tid; idx < 1024; idx += 512) {
        int j = idx >> 5, k = idx & 31;
        sb[j * 33 + k] = w[h * 63 + ((32 - k + j) % 63)];
    }

    asm volatile("cp.async.wait_group 0;\n" ::: "memory");
    __syncthreads();

    // ---- R/C partial sums from smem (512 thr: r x eh x d4) ----
    {
        int r  = tid >> 4;           // 0..31
        int eh = (tid >> 3) & 1;     // 0..1
        int d4 = tid & 7;            // 0..7
        float4 accR = make_float4(0.f, 0.f, 0.f, 0.f);
        float4 accC = make_float4(0.f, 0.f, 0.f, 0.f);
        #pragma unroll
        for (int k = 0; k < 16; ++k) {
            float4 x = sv[(r * 32 + eh * 16 + k) * 8 + d4];   // R: contiguous rows
            float4 y = sv[((eh * 16 + k) * 32 + r) * 8 + d4]; // C: stride-32 rows
            accR.x += x.x; accR.y += x.y; accR.z += x.z; accR.w += x.w;
            accC.x += y.x; accC.y += y.y; accC.z += y.z; accC.w += y.w;
        }
        sRp[eh * 256 + r * 8 + d4] = accR;
        sCp[eh * 256 + r * 8 + d4] = accC;
    }
    __syncthreads();

    // ---- combine eh-partials (512 thr: which x r x d4) ----
    {
        int which = tid >> 8;
        int r  = (tid >> 3) & 31;
        int d4 = tid & 7;
        float4* p = which ? sCp : sRp;
        float4 a = p[r * 8 + d4];
        float4 b = p[256 + r * 8 + d4];
        a.x += b.x; a.y += b.y; a.z += b.z; a.w += b.w;
        p[r * 8 + d4] = a;           // final R/C live in sRp/sCp[0..255]
    }
    __syncthreads();

    // ---- matvec: A = bias@R (which=0), B = bias@C (which=1) ----
    {
        int which = tid >> 8;
        int a  = (tid >> 3) & 31;
        int d4 = tid & 7;
        const float4* src = which ? sCp : sRp;
        float4 acc = make_float4(0.f, 0.f, 0.f, 0.f);
        #pragma unroll
        for (int k = 0; k < 32; ++k) {
            float f = sb[a * 33 + k];
            float4 x = src[k * 8 + d4];
            acc.x = fmaf(f, x.x, acc.x);
            acc.y = fmaf(f, x.y, acc.y);
            acc.z = fmaf(f, x.z, acc.z);
            acc.w = fmaf(f, x.w, acc.w);
        }
        (which ? sB : sA)[a * 8 + d4] = acc;
    }
    __syncthreads();

    // ---- write out: j = i*64 + jg, streaming stores ----
    {
        int jg = tid >> 3;           // 0..63
        int d4 = tid & 7;
        float4* po = out4 + ((size_t)n * 1024) * 128 + h * 16 + q * 8 + d4;
        #pragma unroll
        for (int i = 0; i < 16; ++i) {
            int j = i * 64 + jg;
            int a = j >> 5, b = j & 31;
            float4 x = sA[a * 8 + d4];
            float4 y = sB[b * 8 + d4];
            x.x += y.x; x.y += y.y; x.z += y.z; x.w += y.w;
            __stcs(po + (size_t)j * 128, x);
        }
    }
}

extern "C" void kernel_launch(void* const* d_in, const int* in_sizes, int n_in,
                              void* d_out, int out_size) {
    const float* v = (const float*)d_in[0];
    const float* w = (const float*)d_in[1];
    if (n_in >= 2 && in_sizes[0] < in_sizes[1]) {
        const float* tmp = v; v = w; w = tmp;
    }

    static_assert(SMEM_BYTES <= 227 * 1024, "smem budget");
    cudaFuncSetAttribute(fused_kernel,
                         cudaFuncAttributeMaxDynamicSharedMemorySize, SMEM_BYTES);
    fused_kernel<<<128, 512, SMEM_BYTES>>>((const float4*)v, w, (float4*)d_out);
}